// round 1
// baseline (speedup 1.0000x reference)
#include <cuda_runtime.h>
#include <cuda_bf16.h>
#include <math.h>

#define Hh   8
#define Dm   128
#define Ee   128
#define KDk  16
#define Bb   16
#define NPICK 250
#define NDEL  250
#define Gg   501            // 1 + NPICK + NDEL
#define NTOK (Bb*Gg)        // 8016

// ---------------- device scratch (no allocations allowed) ----------------
__device__ float g_K [Hh*Bb*Gg*KDk];
__device__ float g_V [Hh*Bb*Gg*KDk];
__device__ float g_Qm[Hh*Bb*Gg*KDk];
__device__ float g_QA[Hh*Bb*Gg*KDk];   // scores vs K[1..250]   (W1 for pick rows, W3 for del rows)
__device__ float g_QB[Hh*Bb*Gg*KDk];   // scores vs K[251..500] (W2 for pick rows, W4 for del rows)
__device__ float g_heads[Hh*Bb*Gg*KDk];

// ==========================================================================
// Kernel 1: projections.  One block = (head, 64-token chunk).
// smem: 7 transposed weight mats Wt[m][k][132] (row padded to 132 floats to
// kill bank conflicts) + 64 staged q rows.
// ==========================================================================
#define K1_TOK 64
#define WROW   132
#define K1_SMEM ((7*16*WROW + K1_TOK*Dm)*4)

__global__ void proj_kernel(const float* __restrict__ q,
                            const float* __restrict__ Wq,
                            const float* __restrict__ Wk,
                            const float* __restrict__ Wv,
                            const float* __restrict__ W1,
                            const float* __restrict__ W2,
                            const float* __restrict__ W3,
                            const float* __restrict__ W4)
{
    extern __shared__ float sm[];
    float* Wt = sm;                        // 7*16*132 floats
    float* qs = sm + 7*16*WROW;            // K1_TOK*128 floats

    const int h    = blockIdx.y;
    const int base = blockIdx.x * K1_TOK;
    const int tid  = threadIdx.x;          // 128 threads

    // transpose-load the 7 weight matrices for this head: Wt[m][k][d] = W[m][h][d][k]
    const float* Ws[7] = {Wq, Wk, Wv, W1, W2, W3, W4};
#pragma unroll
    for (int m = 0; m < 7; m++) {
        const float* w = Ws[m] + h * (Dm*KDk);
        for (int idx = tid; idx < Dm*KDk; idx += 128) {
            int d = idx >> 4, k = idx & 15;
            Wt[(m*16 + k)*WROW + d] = w[idx];
        }
    }
    // stage q rows (contiguous in flattened (b*G+g) order)
    const int nTok = min(K1_TOK, NTOK - base);
    const float4* qg  = (const float4*)(q + (size_t)base * Dm);
    float4*       qs4 = (float4*)qs;
    for (int i = tid; i < nTok * (Dm/4); i += 128) qs4[i] = qg[i];
    __syncthreads();

    const int k  = tid & 15;
    const int tl = tid >> 4;               // 8 token lanes
    const float nf = 0.25f;                // 1/sqrt(KD)

    for (int t = tl; t < nTok; t += 8) {
        const int token = base + t;
        const int b = token / Gg;
        const int g = token - b * Gg;
        const bool pick = (g >= 1 && g <= NPICK);
        const int qa = pick ? 3 : 5;
        const int qb = pick ? 4 : 6;

        const float4* q4 = (const float4*)(qs + t * Dm);
        const float4* w0 = (const float4*)(Wt + (0*16 + k)*WROW);
        const float4* w1 = (const float4*)(Wt + (1*16 + k)*WROW);
        const float4* w2 = (const float4*)(Wt + (2*16 + k)*WROW);
        const float4* w3 = (const float4*)(Wt + (qa*16 + k)*WROW);
        const float4* w4 = (const float4*)(Wt + (qb*16 + k)*WROW);

        float a0=0.f, a1=0.f, a2=0.f, a3=0.f, a4=0.f;
#pragma unroll 8
        for (int i = 0; i < 32; i++) {
            float4 qv = q4[i];
            float4 w;
            w = w0[i]; a0 = fmaf(qv.x,w.x,fmaf(qv.y,w.y,fmaf(qv.z,w.z,fmaf(qv.w,w.w,a0))));
            w = w1[i]; a1 = fmaf(qv.x,w.x,fmaf(qv.y,w.y,fmaf(qv.z,w.z,fmaf(qv.w,w.w,a1))));
            w = w2[i]; a2 = fmaf(qv.x,w.x,fmaf(qv.y,w.y,fmaf(qv.z,w.z,fmaf(qv.w,w.w,a2))));
            w = w3[i]; a3 = fmaf(qv.x,w.x,fmaf(qv.y,w.y,fmaf(qv.z,w.z,fmaf(qv.w,w.w,a3))));
            w = w4[i]; a4 = fmaf(qv.x,w.x,fmaf(qv.y,w.y,fmaf(qv.z,w.z,fmaf(qv.w,w.w,a4))));
        }
        const int idx = ((h*Bb + b)*Gg + g)*KDk + k;
        g_Qm[idx] = a0 * nf;
        g_K [idx] = a1;
        g_V [idx] = a2;
        g_QA[idx] = a3 * nf;
        g_QB[idx] = a4 * nf;
    }
}

// ==========================================================================
// Kernel 2: fused attention (online softmax over 501 main + 2x250 extra keys)
// block = (h, b, q-tile of 128); K,V tiles in smem; one query per thread.
// ==========================================================================
#define K2_SMEM (2*Gg*KDk*4)   // 64128 bytes

__device__ __forceinline__ float dot16(const float4& a0, const float4& a1,
                                       const float4& a2, const float4& a3,
                                       const float4* kr)
{
    float4 k0 = kr[0], k1 = kr[1], k2 = kr[2], k3 = kr[3];
    float s0 = fmaf(a0.x,k0.x, a0.y*k0.y); s0 = fmaf(a0.z,k0.z,s0); s0 = fmaf(a0.w,k0.w,s0);
    float s1 = fmaf(a1.x,k1.x, a1.y*k1.y); s1 = fmaf(a1.z,k1.z,s1); s1 = fmaf(a1.w,k1.w,s1);
    float s2 = fmaf(a2.x,k2.x, a2.y*k2.y); s2 = fmaf(a2.z,k2.z,s2); s2 = fmaf(a2.w,k2.w,s2);
    float s3 = fmaf(a3.x,k3.x, a3.y*k3.y); s3 = fmaf(a3.z,k3.z,s3); s3 = fmaf(a3.w,k3.w,s3);
    return (s0 + s1) + (s2 + s3);
}

__device__ __forceinline__ void upd(float s, const float4* vr,
                                    float& m, float& l,
                                    float4& o0, float4& o1, float4& o2, float4& o3)
{
    float4 v0 = vr[0], v1 = vr[1], v2 = vr[2], v3 = vr[3];
    if (s <= m) {
        float p = __expf(s - m);
        l += p;
        o0.x = fmaf(p, v0.x, o0.x); o0.y = fmaf(p, v0.y, o0.y);
        o0.z = fmaf(p, v0.z, o0.z); o0.w = fmaf(p, v0.w, o0.w);
        o1.x = fmaf(p, v1.x, o1.x); o1.y = fmaf(p, v1.y, o1.y);
        o1.z = fmaf(p, v1.z, o1.z); o1.w = fmaf(p, v1.w, o1.w);
        o2.x = fmaf(p, v2.x, o2.x); o2.y = fmaf(p, v2.y, o2.y);
        o2.z = fmaf(p, v2.z, o2.z); o2.w = fmaf(p, v2.w, o2.w);
        o3.x = fmaf(p, v3.x, o3.x); o3.y = fmaf(p, v3.y, o3.y);
        o3.z = fmaf(p, v3.z, o3.z); o3.w = fmaf(p, v3.w, o3.w);
    } else {
        float c = __expf(m - s);
        l = fmaf(l, c, 1.f);
        o0.x = fmaf(o0.x, c, v0.x); o0.y = fmaf(o0.y, c, v0.y);
        o0.z = fmaf(o0.z, c, v0.z); o0.w = fmaf(o0.w, c, v0.w);
        o1.x = fmaf(o1.x, c, v1.x); o1.y = fmaf(o1.y, c, v1.y);
        o1.z = fmaf(o1.z, c, v1.z); o1.w = fmaf(o1.w, c, v1.w);
        o2.x = fmaf(o2.x, c, v2.x); o2.y = fmaf(o2.y, c, v2.y);
        o2.z = fmaf(o2.z, c, v2.z); o2.w = fmaf(o2.w, c, v2.w);
        o3.x = fmaf(o3.x, c, v3.x); o3.y = fmaf(o3.y, c, v3.y);
        o3.z = fmaf(o3.z, c, v3.z); o3.w = fmaf(o3.w, c, v3.w);
        m = s;
    }
}

__global__ void attn_kernel()
{
    extern __shared__ float sm[];
    float4* Ks4 = (float4*)sm;
    float4* Vs4 = (float4*)(sm + Gg*KDk);

    const int h  = blockIdx.z;
    const int b  = blockIdx.y;
    const int qt = blockIdx.x;
    const int tid = threadIdx.x;         // 128 threads
    const int hb  = h*Bb + b;

    const float4* Kg = (const float4*)(g_K + (size_t)hb * Gg * KDk);
    const float4* Vg = (const float4*)(g_V + (size_t)hb * Gg * KDk);
    for (int i = tid; i < Gg*4; i += 128) { Ks4[i] = Kg[i]; Vs4[i] = Vg[i]; }
    __syncthreads();

    const int qrow = qt*128 + tid;
    if (qrow >= Gg) return;

    const int qidx = (hb*Gg + qrow)*KDk;
    const float4* qp;
    qp = (const float4*)(g_Qm + qidx);
    float4 qm0 = qp[0], qm1 = qp[1], qm2 = qp[2], qm3 = qp[3];

    float m = -3.0e38f, l = 0.f;
    float4 o0 = {0,0,0,0}, o1 = {0,0,0,0}, o2 = {0,0,0,0}, o3 = {0,0,0,0};

    // main block: all 501 keys, no zmask
#pragma unroll 4
    for (int g = 0; g < Gg; g++) {
        float s = dot16(qm0, qm1, qm2, qm3, Ks4 + g*4);
        upd(s, Vs4 + g*4, m, l, o0, o1, o2, o3);
    }

    if (qrow >= 1) {
        qp = (const float4*)(g_QA + qidx);
        float4 qa0 = qp[0], qa1 = qp[1], qa2 = qp[2], qa3 = qp[3];
        qp = (const float4*)(g_QB + qidx);
        float4 qb0 = qp[0], qb1 = qp[1], qb2 = qp[2], qb3 = qp[3];

        const float4* Kp = Ks4 + 1*4;
        const float4* Vp = Vs4 + 1*4;
#pragma unroll 4
        for (int j = 0; j < NPICK; j++) {
            float s = dot16(qa0, qa1, qa2, qa3, Kp + j*4);
            if (s != 0.f) upd(s, Vp + j*4, m, l, o0, o1, o2, o3);   // zmask: ==0 -> -inf
        }
        const float4* Kd = Ks4 + (1+NPICK)*4;
        const float4* Vd = Vs4 + (1+NPICK)*4;
#pragma unroll 4
        for (int j = 0; j < NDEL; j++) {
            float s = dot16(qb0, qb1, qb2, qb3, Kd + j*4);
            if (s != 0.f) upd(s, Vd + j*4, m, l, o0, o1, o2, o3);
        }
    }

    const float inv = 1.f / l;
    float4* outp = (float4*)(g_heads + qidx);
    o0.x*=inv; o0.y*=inv; o0.z*=inv; o0.w*=inv;
    o1.x*=inv; o1.y*=inv; o1.z*=inv; o1.w*=inv;
    o2.x*=inv; o2.y*=inv; o2.z*=inv; o2.w*=inv;
    o3.x*=inv; o3.y*=inv; o3.z*=inv; o3.w*=inv;
    outp[0]=o0; outp[1]=o1; outp[2]=o2; outp[3]=o3;
}

// ==========================================================================
// Kernel 3: out[b,g,e] = sum_{h,v} heads[h,b,g,v] * W_out[h,v,e]
// 12 tokens per block, heads staged in smem, W_out via L1 (__ldg).
// 8016 = 668 * 12 exactly.
// ==========================================================================
#define K3_TOK 12

__global__ void out_kernel(const float* __restrict__ Wo, float* __restrict__ out)
{
    __shared__ float hs[K3_TOK][128];
    const int base = blockIdx.x * K3_TOK;
    const int tid  = threadIdx.x;     // 128 threads; tid = output column e

    for (int i = tid; i < K3_TOK*128; i += 128) {
        int t  = i >> 7, hv = i & 127;
        int token = base + t;
        int b = token / Gg, g = token - b*Gg;
        int hh = hv >> 4, v = hv & 15;
        hs[t][hv] = g_heads[((hh*Bb + b)*Gg + g)*KDk + v];
    }
    __syncthreads();

    float acc[K3_TOK];
#pragma unroll
    for (int t = 0; t < K3_TOK; t++) acc[t] = 0.f;

#pragma unroll 4
    for (int hv = 0; hv < 128; hv++) {
        float w = __ldg(Wo + hv*Ee + tid);
#pragma unroll
        for (int t = 0; t < K3_TOK; t++) acc[t] = fmaf(hs[t][hv], w, acc[t]);
    }
#pragma unroll
    for (int t = 0; t < K3_TOK; t++)
        out[(size_t)(base + t)*Ee + tid] = acc[t];
}

// ==========================================================================
extern "C" void kernel_launch(void* const* d_in, const int* in_sizes, int n_in,
                              void* d_out, int out_size)
{
    const float* q  = (const float*)d_in[0];
    const float* Wq = (const float*)d_in[1];
    const float* Wk = (const float*)d_in[2];
    const float* Wv = (const float*)d_in[3];
    const float* W1 = (const float*)d_in[4];
    const float* W2 = (const float*)d_in[5];
    const float* W3 = (const float*)d_in[6];
    const float* W4 = (const float*)d_in[7];
    const float* Wo = (const float*)d_in[8];
    float* out = (float*)d_out;

    cudaFuncSetAttribute(proj_kernel, cudaFuncAttributeMaxDynamicSharedMemorySize, K1_SMEM);
    cudaFuncSetAttribute(attn_kernel, cudaFuncAttributeMaxDynamicSharedMemorySize, K2_SMEM);

    dim3 g1((NTOK + K1_TOK - 1)/K1_TOK, Hh);        // (126, 8)
    proj_kernel<<<g1, 128, K1_SMEM>>>(q, Wq, Wk, Wv, W1, W2, W3, W4);

    dim3 g2((Gg + 127)/128, Bb, Hh);                // (4, 16, 8)
    attn_kernel<<<g2, 128, K2_SMEM>>>();

    out_kernel<<<NTOK / K3_TOK, 128>>>(Wo, out);    // 668 blocks
}

// round 2
// speedup vs baseline: 1.4829x; 1.4829x over previous
#include <cuda_runtime.h>
#include <cuda_bf16.h>
#include <math.h>

#define Hh   8
#define Dm   128
#define Ee   128
#define KDk  16
#define Bb   16
#define NPICK 250
#define NDEL  250
#define Gg   501            // 1 + NPICK + NDEL
#define NTOK (Bb*Gg)        // 8016

typedef unsigned long long u64;

// ---------------- packed f32x2 helpers (FFMA2 path, 2x fp32 rate) ----------
__device__ __forceinline__ u64 fma2(u64 a, u64 b, u64 c) {
    u64 d; asm("fma.rn.f32x2 %0, %1, %2, %3;" : "=l"(d) : "l"(a), "l"(b), "l"(c));
    return d;
}
__device__ __forceinline__ u64 mul2(u64 a, u64 b) {
    u64 d; asm("mul.rn.f32x2 %0, %1, %2;" : "=l"(d) : "l"(a), "l"(b));
    return d;
}
__device__ __forceinline__ u64 add2(u64 a, u64 b) {
    u64 d; asm("add.rn.f32x2 %0, %1, %2;" : "=l"(d) : "l"(a), "l"(b));
    return d;
}
__device__ __forceinline__ void upk(u64 a, float& x, float& y) {
    asm("mov.b64 {%0, %1}, %2;" : "=f"(x), "=f"(y) : "l"(a));
}
__device__ __forceinline__ u64 dup2(float x) {
    u64 r; asm("mov.b64 %0, {%1, %1};" : "=l"(r) : "f"(x));
    return r;
}
__device__ __forceinline__ float ex2f(float x) {
    float r; asm("ex2.approx.ftz.f32 %0, %1;" : "=f"(r) : "f"(x));
    return r;
}

// ---------------- device scratch ----------------
__device__ float g_K [Hh*Bb*Gg*KDk];
__device__ float g_V [Hh*Bb*Gg*KDk];
__device__ float g_Qm[Hh*Bb*Gg*KDk];   // pre-scaled by nf*log2(e)
__device__ float g_QA[Hh*Bb*Gg*KDk];   // pre-scaled; W1 (pick rows) / W3 (del rows)
__device__ float g_QB[Hh*Bb*Gg*KDk];   // pre-scaled; W2 (pick rows) / W4 (del rows)
__device__ float g_heads[Hh*Bb*Gg*KDk];

#define SCL   (0.25f * 1.44269504f)    // 1/sqrt(KD) * log2(e)
#define M2OFF 16.0f                    // fixed softmax offset (log2 units)

// ==========================================================================
// Kernel 1: projections.  Block = (48-token chunk, head), 256 threads.
// thread (k = tid&15, tg = tid>>4): 3 tokens x 7 mats x 1 k, fma2 inner loop.
// 167 * 48 = 8016 exactly -> no bounds checks.
// ==========================================================================
#define PT_TOK 48
#define WPAD   130
#define K1_SMEM ((7*16*WPAD + PT_TOK*Dm)*4)   // 82816 B

__global__ void __launch_bounds__(256) proj_kernel(
    const float* __restrict__ q,
    const float* __restrict__ Wq, const float* __restrict__ Wk,
    const float* __restrict__ Wv, const float* __restrict__ W1,
    const float* __restrict__ W2, const float* __restrict__ W3,
    const float* __restrict__ W4)
{
    extern __shared__ float sm[];
    float* Wt = sm;                         // 7*16*130
    float* qs = sm + 7*16*WPAD;             // 48*128

    const int h    = blockIdx.y;
    const int base = blockIdx.x * PT_TOK;
    const int tid  = threadIdx.x;

    const float* Ws[7] = {Wq, Wk, Wv, W1, W2, W3, W4};
#pragma unroll
    for (int m = 0; m < 7; m++) {
        const float* w = Ws[m] + h * (Dm*KDk);
        for (int idx = tid; idx < Dm*KDk; idx += 256) {
            int d = idx >> 4, kk = idx & 15;
            Wt[(m*16 + kk)*WPAD + d] = w[idx];
        }
    }
    {
        const float4* qg  = (const float4*)(q + (size_t)base * Dm);
        float4*       qs4 = (float4*)qs;
#pragma unroll
        for (int i = 0; i < PT_TOK*Dm/4/256; i++)   // 6 iters
            qs4[tid + i*256] = qg[tid + i*256];
    }
    __syncthreads();

    const int k  = tid & 15;
    const int tg = tid >> 4;                // 16 token groups, 3 tokens each

    u64 acc[3][7];
#pragma unroll
    for (int i = 0; i < 3; i++)
#pragma unroll
        for (int m = 0; m < 7; m++) acc[i][m] = 0ull;

    const u64* qr0 = (const u64*)(qs + (tg*3 + 0)*Dm);
    const u64* qr1 = (const u64*)(qs + (tg*3 + 1)*Dm);
    const u64* qr2 = (const u64*)(qs + (tg*3 + 2)*Dm);
    const u64* wr[7];
#pragma unroll
    for (int m = 0; m < 7; m++) wr[m] = (const u64*)(Wt + (m*16 + k)*WPAD);

#pragma unroll 4
    for (int d2 = 0; d2 < Dm/2; d2++) {
        u64 q0 = qr0[d2], q1 = qr1[d2], q2 = qr2[d2];
#pragma unroll
        for (int m = 0; m < 7; m++) {
            u64 w = wr[m][d2];
            acc[0][m] = fma2(q0, w, acc[0][m]);
            acc[1][m] = fma2(q1, w, acc[1][m]);
            acc[2][m] = fma2(q2, w, acc[2][m]);
        }
    }

#pragma unroll
    for (int i = 0; i < 3; i++) {
        float s[7];
#pragma unroll
        for (int m = 0; m < 7; m++) { float x, y; upk(acc[i][m], x, y); s[m] = x + y; }
        const int token = base + tg*3 + i;
        const int b = token / Gg;
        const int g = token - b * Gg;
        const bool pick = (g >= 1 && g <= NPICK);
        const int idx = ((h*Bb + b)*Gg + g)*KDk + k;
        g_Qm[idx] = s[0] * SCL;
        g_K [idx] = s[1];
        g_V [idx] = s[2];
        g_QA[idx] = (pick ? s[3] : s[5]) * SCL;
        g_QB[idx] = (pick ? s[4] : s[6]) * SCL;
    }
}

// ==========================================================================
// Kernel 2: fused attention.  Fixed-offset exp2 softmax (no running max),
// packed f32x2 dot + AV accumulate.  Block = (q-tile 128, b, h).
// ==========================================================================
#define K2_SMEM (2*Gg*KDk*4)   // 64128 B

__global__ void __launch_bounds__(128) attn_kernel()
{
    extern __shared__ float sm[];

    const int h  = blockIdx.z;
    const int b  = blockIdx.y;
    const int qt = blockIdx.x;
    const int tid = threadIdx.x;
    const int hb  = h*Bb + b;

    {   // stage K,V for this (h,b): 501 x 16 floats each
        const float4* Kg = (const float4*)(g_K + (size_t)hb * Gg * KDk);
        const float4* Vg = (const float4*)(g_V + (size_t)hb * Gg * KDk);
        float4* Ks4 = (float4*)sm;
        float4* Vs4 = (float4*)(sm + Gg*KDk);
        for (int i = tid; i < Gg*4; i += 128) { Ks4[i] = Kg[i]; Vs4[i] = Vg[i]; }
    }
    __syncthreads();

    const int qrow = qt*128 + tid;
    if (qrow >= Gg) return;

    const u64* Ks = (const u64*)sm;            // 8 pairs per key row
    const u64* Vs = Ks + Gg*8;

    const int qidx = (hb*Gg + qrow)*KDk;
    u64 qm[8];
    {
        const u64* qp = (const u64*)(g_Qm + qidx);
#pragma unroll
        for (int j = 0; j < 8; j++) qm[j] = qp[j];
    }

    float l = 0.f;
    u64 o[8];
#pragma unroll
    for (int j = 0; j < 8; j++) o[j] = 0ull;

    // ---- main block: 501 keys, no mask ----
#pragma unroll 2
    for (int g = 0; g < Gg; g++) {
        const u64* kr = Ks + g*8;
        u64 a0 = mul2(qm[0], kr[0]);
        u64 a1 = mul2(qm[1], kr[1]);
        a0 = fma2(qm[2], kr[2], a0);
        a1 = fma2(qm[3], kr[3], a1);
        a0 = fma2(qm[4], kr[4], a0);
        a1 = fma2(qm[5], kr[5], a1);
        a0 = fma2(qm[6], kr[6], a0);
        a1 = fma2(qm[7], kr[7], a1);
        a0 = add2(a0, a1);
        float x, y; upk(a0, x, y);
        float s = x + y;
        float p = ex2f(s - M2OFF);
        l += p;
        u64 pp = dup2(p);
        const u64* vr = Vs + g*8;
#pragma unroll
        for (int j = 0; j < 8; j++) o[j] = fma2(pp, vr[j], o[j]);
    }

    // ---- extra blocks (rows 1..500 only), zmask: score==0 -> excluded ----
    if (qrow >= 1) {
        u64 qa[8], qb[8];
        {
            const u64* pa = (const u64*)(g_QA + qidx);
            const u64* pb = (const u64*)(g_QB + qidx);
#pragma unroll
            for (int j = 0; j < 8; j++) { qa[j] = pa[j]; qb[j] = pb[j]; }
        }
        const u64* Kp = Ks + 1*8;
        const u64* Vp = Vs + 1*8;
#pragma unroll 2
        for (int g = 0; g < NPICK; g++) {
            const u64* kr = Kp + g*8;
            u64 a0 = mul2(qa[0], kr[0]);
            u64 a1 = mul2(qa[1], kr[1]);
            a0 = fma2(qa[2], kr[2], a0);
            a1 = fma2(qa[3], kr[3], a1);
            a0 = fma2(qa[4], kr[4], a0);
            a1 = fma2(qa[5], kr[5], a1);
            a0 = fma2(qa[6], kr[6], a0);
            a1 = fma2(qa[7], kr[7], a1);
            a0 = add2(a0, a1);
            float x, y; upk(a0, x, y);
            float s = x + y;
            float p = ex2f(s - M2OFF);
            p = (s == 0.f) ? 0.f : p;
            l += p;
            u64 pp = dup2(p);
            const u64* vr = Vp + g*8;
#pragma unroll
            for (int j = 0; j < 8; j++) o[j] = fma2(pp, vr[j], o[j]);
        }
        const u64* Kd = Ks + (1+NPICK)*8;
        const u64* Vd = Vs + (1+NPICK)*8;
#pragma unroll 2
        for (int g = 0; g < NDEL; g++) {
            const u64* kr = Kd + g*8;
            u64 a0 = mul2(qb[0], kr[0]);
            u64 a1 = mul2(qb[1], kr[1]);
            a0 = fma2(qb[2], kr[2], a0);
            a1 = fma2(qb[3], kr[3], a1);
            a0 = fma2(qb[4], kr[4], a0);
            a1 = fma2(qb[5], kr[5], a1);
            a0 = fma2(qb[6], kr[6], a0);
            a1 = fma2(qb[7], kr[7], a1);
            a0 = add2(a0, a1);
            float x, y; upk(a0, x, y);
            float s = x + y;
            float p = ex2f(s - M2OFF);
            p = (s == 0.f) ? 0.f : p;
            l += p;
            u64 pp = dup2(p);
            const u64* vr = Vd + g*8;
#pragma unroll
            for (int j = 0; j < 8; j++) o[j] = fma2(pp, vr[j], o[j]);
        }
    }

    const float inv = 1.f / l;
    const u64 iv = dup2(inv);
    u64* outp = (u64*)(g_heads + qidx);
#pragma unroll
    for (int j = 0; j < 8; j++) outp[j] = mul2(o[j], iv);
}

// ==========================================================================
// Kernel 3: out[b,g,e] = sum_{h,v} heads[h,b,g,v] * W_out[h,v,e]
// ==========================================================================
#define K3_TOK 12

__global__ void out_kernel(const float* __restrict__ Wo, float* __restrict__ out)
{
    __shared__ float hs[K3_TOK][128];
    const int base = blockIdx.x * K3_TOK;
    const int tid  = threadIdx.x;     // 128 threads; tid = output column e

    for (int i = tid; i < K3_TOK*128; i += 128) {
        int t  = i >> 7, hv = i & 127;
        int token = base + t;
        int b = token / Gg, g = token - b*Gg;
        int hh = hv >> 4, v = hv & 15;
        hs[t][hv] = g_heads[((hh*Bb + b)*Gg + g)*KDk + v];
    }
    __syncthreads();

    float acc[K3_TOK];
#pragma unroll
    for (int t = 0; t < K3_TOK; t++) acc[t] = 0.f;

#pragma unroll 4
    for (int hv = 0; hv < 128; hv++) {
        float w = __ldg(Wo + hv*Ee + tid);
#pragma unroll
        for (int t = 0; t < K3_TOK; t++) acc[t] = fmaf(hs[t][hv], w, acc[t]);
    }
#pragma unroll
    for (int t = 0; t < K3_TOK; t++)
        out[(size_t)(base + t)*Ee + tid] = acc[t];
}

// ==========================================================================
extern "C" void kernel_launch(void* const* d_in, const int* in_sizes, int n_in,
                              void* d_out, int out_size)
{
    const float* q  = (const float*)d_in[0];
    const float* Wq = (const float*)d_in[1];
    const float* Wk = (const float*)d_in[2];
    const float* Wv = (const float*)d_in[3];
    const float* W1 = (const float*)d_in[4];
    const float* W2 = (const float*)d_in[5];
    const float* W3 = (const float*)d_in[6];
    const float* W4 = (const float*)d_in[7];
    const float* Wo = (const float*)d_in[8];
    float* out = (float*)d_out;

    cudaFuncSetAttribute(proj_kernel, cudaFuncAttributeMaxDynamicSharedMemorySize, K1_SMEM);
    cudaFuncSetAttribute(attn_kernel, cudaFuncAttributeMaxDynamicSharedMemorySize, K2_SMEM);

    dim3 g1(NTOK / PT_TOK, Hh);                     // (167, 8)
    proj_kernel<<<g1, 256, K1_SMEM>>>(q, Wq, Wk, Wv, W1, W2, W3, W4);

    dim3 g2((Gg + 127)/128, Bb, Hh);                // (4, 16, 8)
    attn_kernel<<<g2, 128, K2_SMEM>>>();

    out_kernel<<<NTOK / K3_TOK, 128>>>(Wo, out);    // 668 blocks
}

// round 3
// speedup vs baseline: 1.8501x; 1.2477x over previous
#include <cuda_runtime.h>
#include <cuda_bf16.h>
#include <math.h>

#define Hh   8
#define Dm   128
#define Ee   128
#define KDk  16
#define Bb   16
#define NPICK 250
#define NDEL  250
#define Gg   501            // 1 + NPICK + NDEL
#define NTOK (Bb*Gg)        // 8016

typedef unsigned long long u64;

// ---------------- packed f32x2 helpers (FFMA2 path, 2x fp32 rate) ----------
__device__ __forceinline__ u64 fma2(u64 a, u64 b, u64 c) {
    u64 d; asm("fma.rn.f32x2 %0, %1, %2, %3;" : "=l"(d) : "l"(a), "l"(b), "l"(c));
    return d;
}
__device__ __forceinline__ u64 mul2(u64 a, u64 b) {
    u64 d; asm("mul.rn.f32x2 %0, %1, %2;" : "=l"(d) : "l"(a), "l"(b));
    return d;
}
__device__ __forceinline__ u64 add2(u64 a, u64 b) {
    u64 d; asm("add.rn.f32x2 %0, %1, %2;" : "=l"(d) : "l"(a), "l"(b));
    return d;
}
__device__ __forceinline__ void upk(u64 a, float& x, float& y) {
    asm("mov.b64 {%0, %1}, %2;" : "=f"(x), "=f"(y) : "l"(a));
}
__device__ __forceinline__ u64 dup2(float x) {
    u64 r; asm("mov.b64 %0, {%1, %1};" : "=l"(r) : "f"(x));
    return r;
}
__device__ __forceinline__ float ex2f(float x) {
    float r; asm("ex2.approx.ftz.f32 %0, %1;" : "=f"(r) : "f"(x));
    return r;
}

// ---------------- device scratch ----------------
#define WPAD 130
__device__ float g_Wt[Hh*7*KDk*WPAD];  // transposed+padded weights [h][m*16+k][WPAD]
__device__ float g_K [Hh*Bb*Gg*KDk];
__device__ float g_V [Hh*Bb*Gg*KDk];
__device__ float g_Qm[Hh*Bb*Gg*KDk];   // pre-scaled by nf*log2(e)
__device__ float g_QA[Hh*Bb*Gg*KDk];   // pre-scaled; W1 (pick rows) / W3 (del rows)
__device__ float g_QB[Hh*Bb*Gg*KDk];   // pre-scaled; W2 (pick rows) / W4 (del rows)
__device__ float g_heads[Hh*Bb*Gg*KDk];

#define SCL   (0.25f * 1.44269504f)    // 1/sqrt(KD) * log2(e)
#define M2OFF 16.0f                    // fixed softmax offset (log2 units)

// ==========================================================================
// Kernel 0: weight prep.  g_Wt[h][m*16+k][d] = W_m[h][d][k]  (row pad 130)
// grid (7, 8), 256 threads.
// ==========================================================================
__global__ void wprep_kernel(const float* __restrict__ Wq, const float* __restrict__ Wk,
                             const float* __restrict__ Wv, const float* __restrict__ W1,
                             const float* __restrict__ W2, const float* __restrict__ W3,
                             const float* __restrict__ W4)
{
    const float* Ws[7] = {Wq, Wk, Wv, W1, W2, W3, W4};
    const int m = blockIdx.x, h = blockIdx.y;
    const float* w = Ws[m] + h * (Dm*KDk);
    float* dst = g_Wt + (size_t)(h*7*KDk + m*KDk) * WPAD;
    for (int idx = threadIdx.x; idx < Dm*KDk; idx += 256) {
        int d = idx >> 4, k = idx & 15;
        dst[k*WPAD + d] = w[idx];
    }
}

// ==========================================================================
// Kernel 1: projections.  Block = (80-token chunk, head), 256 threads.
// thread (k = tid&15, tg = tid>>4): 5 tokens x 7 mats x 1 k, fma2 inner loop.
// ==========================================================================
#define PT_TOK 80
#define K1_SMEM ((7*16*WPAD + PT_TOK*Dm)*4)   // 99200 B

__global__ void __launch_bounds__(256) proj_kernel(const float* __restrict__ q)
{
    extern __shared__ float sm[];
    float* Wt = sm;                         // 112*130
    float* qs = sm + 7*KDk*WPAD;            // 80*128

    const int h    = blockIdx.y;
    const int base = blockIdx.x * PT_TOK;
    const int tid  = threadIdx.x;
    const int nTok = min(PT_TOK, NTOK - base);

    {   // stage padded weights (contiguous float2 copy, L2-hot)
        const float2* src = (const float2*)(g_Wt + (size_t)h*7*KDk*WPAD);
        float2*       dst = (float2*)Wt;
#pragma unroll
        for (int i = 0; i < 29; i++) {      // 29*256 = 7424 >= 7280
            int idx = tid + i*256;
            if (idx < 7*KDk*WPAD/2) dst[idx] = src[idx];
        }
    }
    {   // stage q rows
        const float4* qg  = (const float4*)(q + (size_t)base * Dm);
        float4*       qs4 = (float4*)qs;
        const int n4 = nTok * (Dm/4);
        for (int i = tid; i < n4; i += 256) qs4[i] = qg[i];
    }
    __syncthreads();

    const int k  = tid & 15;
    const int tg = tid >> 4;                // 16 groups x 5 tokens
    const int t0 = tg * 5;

    u64 acc[5][7];
#pragma unroll
    for (int i = 0; i < 5; i++)
#pragma unroll
        for (int m = 0; m < 7; m++) acc[i][m] = 0ull;

    const u64* qr[5];
#pragma unroll
    for (int i = 0; i < 5; i++) qr[i] = (const u64*)(qs + (t0 + i)*Dm);
    const u64* wr[7];
#pragma unroll
    for (int m = 0; m < 7; m++) wr[m] = (const u64*)(Wt + (m*16 + k)*WPAD);

#pragma unroll 2
    for (int d2 = 0; d2 < Dm/2; d2++) {
        u64 qv[5];
#pragma unroll
        for (int i = 0; i < 5; i++) qv[i] = qr[i][d2];
#pragma unroll
        for (int m = 0; m < 7; m++) {
            u64 w = wr[m][d2];
#pragma unroll
            for (int i = 0; i < 5; i++) acc[i][m] = fma2(qv[i], w, acc[i][m]);
        }
    }

#pragma unroll
    for (int i = 0; i < 5; i++) {
        if (t0 + i >= nTok) break;
        float s[7];
#pragma unroll
        for (int m = 0; m < 7; m++) { float x, y; upk(acc[i][m], x, y); s[m] = x + y; }
        const int token = base + t0 + i;
        const int b = token / Gg;
        const int g = token - b * Gg;
        const bool pick = (g >= 1 && g <= NPICK);
        const int idx = ((h*Bb + b)*Gg + g)*KDk + k;
        g_Qm[idx] = s[0] * SCL;
        g_K [idx] = s[1];
        g_V [idx] = s[2];
        g_QA[idx] = (pick ? s[3] : s[5]) * SCL;
        g_QB[idx] = (pick ? s[4] : s[6]) * SCL;
    }
}

// ==========================================================================
// Kernel 2: fused attention.  One block per (h,b), 512 threads, one q-row
// per thread.  Fixed-offset exp2 softmax, packed f32x2 dot + AV accumulate.
// ==========================================================================
#define K2_SMEM (2*Gg*KDk*4)   // 64128 B

__global__ void __launch_bounds__(512) attn_kernel()
{
    extern __shared__ float sm[];

    const int b  = blockIdx.x;
    const int h  = blockIdx.y;
    const int tid = threadIdx.x;
    const int hb  = h*Bb + b;

    {   // stage K,V for this (h,b): 501 x 16 floats each
        const float4* Kg = (const float4*)(g_K + (size_t)hb * Gg * KDk);
        const float4* Vg = (const float4*)(g_V + (size_t)hb * Gg * KDk);
        float4* Ks4 = (float4*)sm;
        float4* Vs4 = (float4*)(sm + Gg*KDk);
        for (int i = tid; i < Gg*4; i += 512) { Ks4[i] = Kg[i]; Vs4[i] = Vg[i]; }
    }
    __syncthreads();

    const int qrow = tid;
    if (qrow >= Gg) return;

    const u64* Ks = (const u64*)sm;            // 8 pairs per key row
    const u64* Vs = Ks + Gg*8;

    const int qidx = (hb*Gg + qrow)*KDk;
    u64 qm[8];
    {
        const u64* qp = (const u64*)(g_Qm + qidx);
#pragma unroll
        for (int j = 0; j < 8; j++) qm[j] = qp[j];
    }

    float l = 0.f;
    u64 o[8];
#pragma unroll
    for (int j = 0; j < 8; j++) o[j] = 0ull;

    // ---- main block: 501 keys, no mask ----
#pragma unroll 2
    for (int g = 0; g < Gg; g++) {
        const u64* kr = Ks + g*8;
        u64 a0 = mul2(qm[0], kr[0]);
        u64 a1 = mul2(qm[1], kr[1]);
        a0 = fma2(qm[2], kr[2], a0);
        a1 = fma2(qm[3], kr[3], a1);
        a0 = fma2(qm[4], kr[4], a0);
        a1 = fma2(qm[5], kr[5], a1);
        a0 = fma2(qm[6], kr[6], a0);
        a1 = fma2(qm[7], kr[7], a1);
        a0 = add2(a0, a1);
        float x, y; upk(a0, x, y);
        float s = x + y;
        float p = ex2f(s - M2OFF);
        l += p;
        u64 pp = dup2(p);
        const u64* vr = Vs + g*8;
#pragma unroll
        for (int j = 0; j < 8; j++) o[j] = fma2(pp, vr[j], o[j]);
    }

    // ---- extra blocks (rows 1..500 only), zmask: score==0 -> excluded ----
    if (qrow >= 1) {
        u64 qa[8], qb[8];
        {
            const u64* pa = (const u64*)(g_QA + qidx);
            const u64* pb = (const u64*)(g_QB + qidx);
#pragma unroll
            for (int j = 0; j < 8; j++) { qa[j] = pa[j]; qb[j] = pb[j]; }
        }
        const u64* Kp = Ks + 1*8;
        const u64* Vp = Vs + 1*8;
#pragma unroll 2
        for (int g = 0; g < NPICK; g++) {
            const u64* kr = Kp + g*8;
            u64 a0 = mul2(qa[0], kr[0]);
            u64 a1 = mul2(qa[1], kr[1]);
            a0 = fma2(qa[2], kr[2], a0);
            a1 = fma2(qa[3], kr[3], a1);
            a0 = fma2(qa[4], kr[4], a0);
            a1 = fma2(qa[5], kr[5], a1);
            a0 = fma2(qa[6], kr[6], a0);
            a1 = fma2(qa[7], kr[7], a1);
            a0 = add2(a0, a1);
            float x, y; upk(a0, x, y);
            float s = x + y;
            float p = ex2f(s - M2OFF);
            p = (s == 0.f) ? 0.f : p;
            l += p;
            u64 pp = dup2(p);
            const u64* vr = Vp + g*8;
#pragma unroll
            for (int j = 0; j < 8; j++) o[j] = fma2(pp, vr[j], o[j]);
        }
        const u64* Kd = Ks + (1+NPICK)*8;
        const u64* Vd = Vs + (1+NPICK)*8;
#pragma unroll 2
        for (int g = 0; g < NDEL; g++) {
            const u64* kr = Kd + g*8;
            u64 a0 = mul2(qb[0], kr[0]);
            u64 a1 = mul2(qb[1], kr[1]);
            a0 = fma2(qb[2], kr[2], a0);
            a1 = fma2(qb[3], kr[3], a1);
            a0 = fma2(qb[4], kr[4], a0);
            a1 = fma2(qb[5], kr[5], a1);
            a0 = fma2(qb[6], kr[6], a0);
            a1 = fma2(qb[7], kr[7], a1);
            a0 = add2(a0, a1);
            float x, y; upk(a0, x, y);
            float s = x + y;
            float p = ex2f(s - M2OFF);
            p = (s == 0.f) ? 0.f : p;
            l += p;
            u64 pp = dup2(p);
            const u64* vr = Vd + g*8;
#pragma unroll
            for (int j = 0; j < 8; j++) o[j] = fma2(pp, vr[j], o[j]);
        }
    }

    const float inv = 1.f / l;
    const u64 iv = dup2(inv);
    u64* outp = (u64*)(g_heads + qidx);
#pragma unroll
    for (int j = 0; j < 8; j++) outp[j] = mul2(o[j], iv);
}

// ==========================================================================
// Kernel 3: out[b,g,e] = sum_{h,v} heads[h,b,g,v] * W_out[h,v,e]
// ==========================================================================
#define K3_TOK 12

__global__ void out_kernel(const float* __restrict__ Wo, float* __restrict__ out)
{
    __shared__ float hs[K3_TOK][128];
    const int base = blockIdx.x * K3_TOK;
    const int tid  = threadIdx.x;     // 128 threads; tid = output column e

    for (int i = tid; i < K3_TOK*128; i += 128) {
        int t  = i >> 7, hv = i & 127;
        int token = base + t;
        int b = token / Gg, g = token - b*Gg;
        int hh = hv >> 4, v = hv & 15;
        hs[t][hv] = g_heads[((hh*Bb + b)*Gg + g)*KDk + v];
    }
    __syncthreads();

    float acc[K3_TOK];
#pragma unroll
    for (int t = 0; t < K3_TOK; t++) acc[t] = 0.f;

#pragma unroll 4
    for (int hv = 0; hv < 128; hv++) {
        float w = __ldg(Wo + hv*Ee + tid);
#pragma unroll
        for (int t = 0; t < K3_TOK; t++) acc[t] = fmaf(hs[t][hv], w, acc[t]);
    }
#pragma unroll
    for (int t = 0; t < K3_TOK; t++)
        out[(size_t)(base + t)*Ee + tid] = acc[t];
}

// ==========================================================================
extern "C" void kernel_launch(void* const* d_in, const int* in_sizes, int n_in,
                              void* d_out, int out_size)
{
    const float* q  = (const float*)d_in[0];
    const float* Wq = (const float*)d_in[1];
    const float* Wk = (const float*)d_in[2];
    const float* Wv = (const float*)d_in[3];
    const float* W1 = (const float*)d_in[4];
    const float* W2 = (const float*)d_in[5];
    const float* W3 = (const float*)d_in[6];
    const float* W4 = (const float*)d_in[7];
    const float* Wo = (const float*)d_in[8];
    float* out = (float*)d_out;

    cudaFuncSetAttribute(proj_kernel, cudaFuncAttributeMaxDynamicSharedMemorySize, K1_SMEM);
    cudaFuncSetAttribute(attn_kernel, cudaFuncAttributeMaxDynamicSharedMemorySize, K2_SMEM);

    dim3 g0(7, Hh);
    wprep_kernel<<<g0, 256>>>(Wq, Wk, Wv, W1, W2, W3, W4);

    dim3 g1((NTOK + PT_TOK - 1)/PT_TOK, Hh);        // (101, 8)
    proj_kernel<<<g1, 256, K1_SMEM>>>(q);

    dim3 g2(Bb, Hh);                                // (16, 8) x 512 threads
    attn_kernel<<<g2, 512, K2_SMEM>>>();

    out_kernel<<<NTOK / K3_TOK, 128>>>(Wo, out);    // 668 blocks
}